// round 7
// baseline (speedup 1.0000x reference)
#include <cuda_runtime.h>
#include <cuda_fp16.h>
#include <math.h>

#define NN 8192
#define TPB 256
#define RPB 4                     // rows per CTA
#define JPT (NN / TPB)            // 32 j's per thread

typedef unsigned long long u64;

// Packed per-point data: {theta, tau, cos(theta), sin(theta)}
__device__ __align__(16) float4 g_packed[NN];

__global__ void prep_kernel(const float* __restrict__ theta,
                            const float* __restrict__ tau) {
    int i = blockIdx.x * blockDim.x + threadIdx.x;
    if (i < NN) {
        float t = theta[i];
        float s, c;
        sincosf(t, &s, &c);
        g_packed[i] = make_float4(t, tau[i], c, s);
    }
}

__device__ __forceinline__ float ex2a(float x) {
    float r; asm("ex2.approx.f32 %0, %1;" : "=f"(r) : "f"(x)); return r;
}
__device__ __forceinline__ float rsqa(float x) {
    float r; asm("rsqrt.approx.f32 %0, %1;" : "=f"(r) : "f"(x)); return r;
}
__device__ __forceinline__ unsigned pack_h2(float a, float b) {
    unsigned r;
    asm("cvt.rn.f16x2.f32 %0, %2, %1;" : "=r"(r) : "f"(a), "f"(b));  // lo=a, hi=b
    return r;
}
// ---- packed f32x2 helpers (Blackwell FFMA2 path) ----
__device__ __forceinline__ u64 pk2(float lo, float hi) {
    u64 r; asm("mov.b64 %0, {%1,%2};" : "=l"(r) : "f"(lo), "f"(hi)); return r;
}
__device__ __forceinline__ u64 bc2(float v) {
    u64 r; asm("mov.b64 %0, {%1,%1};" : "=l"(r) : "f"(v)); return r;
}
__device__ __forceinline__ void unpk(float& lo, float& hi, u64 v) {
    asm("mov.b64 {%0,%1}, %2;" : "=f"(lo), "=f"(hi) : "l"(v));
}
__device__ __forceinline__ u64 addx2(u64 a, u64 b) {
    u64 r; asm("add.rn.f32x2 %0, %1, %2;" : "=l"(r) : "l"(a), "l"(b)); return r;
}
__device__ __forceinline__ u64 fmx2(u64 a, u64 b, u64 c) {
    u64 r; asm("fma.rn.f32x2 %0, %1, %2, %3;" : "=l"(r) : "l"(a), "l"(b), "l"(c)); return r;
}

__device__ __forceinline__ float warp_sum(float v) {
#pragma unroll
    for (int o = 16; o > 0; o >>= 1) v += __shfl_down_sync(0xffffffffu, v, o);
    return v;
}

__global__ void __launch_bounds__(TPB, 3)
row_kernel(float* __restrict__ out_theta,
           float* __restrict__ out_tau,
           float* __restrict__ out_attn) {
    // scores: rows packed pairwise as f16x2 (row0|row1, row2|row3)
    __shared__ __align__(16) unsigned sm01[NN];
    __shared__ __align__(16) unsigned sm23[NN];
    __shared__ float red[6 * RPB][TPB / 32];
    __shared__ float sm_inv[RPB];

    const int i0 = blockIdx.x * RPB;
    const int t  = threadIdx.x;

    float th[RPB], ta[RPB], ci[RPB], si[RPB];
#pragma unroll
    for (int r = 0; r < RPB; r++) {
        const float4 p = g_packed[i0 + r];
        th[r] = p.x; ta[r] = p.y; ci[r] = p.z; si[r] = p.w;
    }

    const float PI_F    = 3.14159265358979323846f;
    const float CEXP    = -3.60673760222240851f;    // -2.5 * log2(e)
    const float NCEXP   = 3.60673760222240851f;     // -CEXP
    const float C3TAU   = 0.3f * CEXP;
    const float CEXP_PI = CEXP * PI_F;              // folded constant
    const float DK      = PI_F + 0.1f;              // d = DK - |y|

    // packed accumulators: lo = even row of pair, hi = odd row
    u64 sum01 = 0, sum23 = 0, ax01 = 0, ax23 = 0;
    u64 ay01 = 0, ay23 = 0, at01 = 0, at23 = 0;
    float fx[RPB], fy[RPB];
#pragma unroll
    for (int r = 0; r < RPB; r++) { fx[r] = 0.f; fy[r] = 0.f; }

#pragma unroll 4
    for (int k = 0; k < JPT; k++) {
        const int j = t + k * TPB;
        const float4 pj = g_packed[j];
        const u64 cj2 = bc2(pj.z);
        const u64 sj2 = bc2(pj.w);
        const u64 tj2 = bc2(pj.y);

        float e[RPB];
#pragma unroll
        for (int r = 0; r < RPB; r++) {
            // y = |dtheta| - pi ; dth = pi - |y| (never materialized)
            float y    = fabsf(th[r] - pj.x) - PI_F;
            float dta  = ta[r] - pj.y;
            float t1   = fmaf(fabsf(dta), C3TAU, CEXP_PI);
            float arg  = fmaf(fabsf(y), NCEXP, t1);     // = CEXP*dth + C3TAU*|dta|
            float ev   = ex2a(arg);                     // MUFU.EX2
            e[r] = ev;

            // repulsion: w = rsqrt(n2 * d^4); +1e-32 keeps j==i contribution exact 0
            float d    = DK - fabsf(y);                 // dth + 0.1
            float d2   = d * d;
            float d4   = d2 * d2;
            float dx   = ci[r] - pj.z;
            float dy   = si[r] - pj.w;
            float n2   = fmaf(dx, dx, dy * dy);
            float w    = rsqa(fmaf(n2, d4, 1e-32f));    // MUFU.RSQ
            fx[r] = fmaf(w, dx, fx[r]);
            fy[r] = fmaf(w, dy, fy[r]);
        }

        // packed linear accumulators (2 rows per instruction)
        const u64 e01 = pk2(e[0], e[1]);
        const u64 e23 = pk2(e[2], e[3]);
        sum01 = addx2(sum01, e01);
        sum23 = addx2(sum23, e23);
        ax01  = fmx2(e01, cj2, ax01);
        ax23  = fmx2(e23, cj2, ax23);
        ay01  = fmx2(e01, sj2, ay01);
        ay23  = fmx2(e23, sj2, ay23);
        at01  = fmx2(e01, tj2, at01);
        at23  = fmx2(e23, tj2, at23);

        sm01[j] = pack_h2(e[0], e[1]);                  // one STS.32 per 2 rows
        sm23[j] = pack_h2(e[2], e[3]);
    }

    // unpack packed accumulators -> per-row scalars
    float sum[RPB], ax[RPB], ay[RPB], at[RPB];
    unpk(sum[0], sum[1], sum01); unpk(sum[2], sum[3], sum23);
    unpk(ax[0],  ax[1],  ax01);  unpk(ax[2],  ax[3],  ax23);
    unpk(ay[0],  ay[1],  ay01);  unpk(ay[2],  ay[3],  ay23);
    unpk(at[0],  at[1],  at01);  unpk(at[2],  at[3],  at23);

    // block reduction: 24 quantities
    const int lane = t & 31, wid = t >> 5;
#pragma unroll
    for (int r = 0; r < RPB; r++) {
        float a0 = warp_sum(sum[r]), a1 = warp_sum(ax[r]), a2 = warp_sum(ay[r]);
        float a3 = warp_sum(at[r]),  a4 = warp_sum(fx[r]), a5 = warp_sum(fy[r]);
        if (lane == 0) {
            red[6 * r + 0][wid] = a0; red[6 * r + 1][wid] = a1;
            red[6 * r + 2][wid] = a2; red[6 * r + 3][wid] = a3;
            red[6 * r + 4][wid] = a4; red[6 * r + 5][wid] = a5;
        }
    }
    __syncthreads();

    if (t < RPB) {
        const int r = t;
        float S = 0.f, AX = 0.f, AY = 0.f, AT = 0.f, FX = 0.f, FY = 0.f;
#pragma unroll
        for (int w = 0; w < TPB / 32; w++) {
            S  += red[6 * r + 0][w]; AX += red[6 * r + 1][w];
            AY += red[6 * r + 2][w]; AT += red[6 * r + 3][w];
            FX += red[6 * r + 4][w]; FY += red[6 * r + 5][w];
        }
        // remove self contribution (e(i,i)~1 to ~1e-6, repel(i,i)=0 exactly)
        S  -= 1.0f;
        AX -= ci[r];
        AY -= si[r];
        AT -= ta[r];

        const float inv = 1.0f / S;
        const float Rx = fmaf(AX, inv, 0.15f * FX);
        const float Ry = fmaf(AY, inv, 0.15f * FY);
        const int i = i0 + r;
        out_theta[i] = atan2f(Ry, Rx);
        out_tau[i]   = AT * inv;
        sm_inv[r] = inv;
        // zero this row's half of the packed diagonal word
        if (r < 2) sm01[i] &= (r & 1) ? 0x0000FFFFu : 0xFFFF0000u;
        else       sm23[i] &= (r & 1) ? 0x0000FFFFu : 0xFFFF0000u;
    }
    __syncthreads();

    // write pass: unpack f16x2 -> two rows at once, coalesced float4 stores
    const float inv0 = sm_inv[0], inv1 = sm_inv[1];
    const float inv2 = sm_inv[2], inv3 = sm_inv[3];
    float4* row0 = reinterpret_cast<float4*>(out_attn + (size_t)(i0 + 0) * NN);
    float4* row1 = reinterpret_cast<float4*>(out_attn + (size_t)(i0 + 1) * NN);
    float4* row2 = reinterpret_cast<float4*>(out_attn + (size_t)(i0 + 2) * NN);
    float4* row3 = reinterpret_cast<float4*>(out_attn + (size_t)(i0 + 3) * NN);
    const uint4* s01 = reinterpret_cast<const uint4*>(sm01);
    const uint4* s23 = reinterpret_cast<const uint4*>(sm23);

#pragma unroll
    for (int k = 0; k < NN / 4 / TPB; k++) {
        const int idx = t + k * TPB;
        {
            uint4 v = s01[idx];
            float2 a = __half22float2(*reinterpret_cast<__half2*>(&v.x));
            float2 b = __half22float2(*reinterpret_cast<__half2*>(&v.y));
            float2 c = __half22float2(*reinterpret_cast<__half2*>(&v.z));
            float2 d = __half22float2(*reinterpret_cast<__half2*>(&v.w));
            row0[idx] = make_float4(a.x * inv0, b.x * inv0, c.x * inv0, d.x * inv0);
            row1[idx] = make_float4(a.y * inv1, b.y * inv1, c.y * inv1, d.y * inv1);
        }
        {
            uint4 v = s23[idx];
            float2 a = __half22float2(*reinterpret_cast<__half2*>(&v.x));
            float2 b = __half22float2(*reinterpret_cast<__half2*>(&v.y));
            float2 c = __half22float2(*reinterpret_cast<__half2*>(&v.z));
            float2 d = __half22float2(*reinterpret_cast<__half2*>(&v.w));
            row2[idx] = make_float4(a.x * inv2, b.x * inv2, c.x * inv2, d.x * inv2);
            row3[idx] = make_float4(a.y * inv3, b.y * inv3, c.y * inv3, d.y * inv3);
        }
    }
}

extern "C" void kernel_launch(void* const* d_in, const int* in_sizes, int n_in,
                              void* d_out, int out_size) {
    const float* theta = (const float*)d_in[0];
    const float* tau   = (const float*)d_in[1];
    float* out = (float*)d_out;

    float* out_theta = out;
    float* out_tau   = out + NN;
    float* out_attn  = out + 2 * NN;

    prep_kernel<<<(NN + 255) / 256, 256>>>(theta, tau);
    row_kernel<<<NN / RPB, TPB>>>(out_theta, out_tau, out_attn);
}